// round 2
// baseline (speedup 1.0000x reference)
#include <cuda_runtime.h>
#include <math.h>

#define N_ 20000
#define E_ 320000
#define T_ 5
#define FO_ 20
#define B_ 50
#define H_ 100
#define FI_ 16
#define EPSF 1e-5f
#define FPAD 104

__device__ float g_P[(size_t)N_ * 1000];     // [n][0..Tg)=P_i, [Tg..2Tg)=P_j
__device__ float g_AGG[(size_t)N_ * 2000];   // [n][t][mean|min|max|std] (4f per tower)
__device__ float g_XH[N_ * H_];
__device__ float g_XA[N_ * H_];
__device__ float g_XB[N_ * H_];
__device__ int   g_cnt[N_];
__device__ int   g_rowoff[N_ + 1];
__device__ int   g_wp[N_];
__device__ int   g_csrs[E_];
__device__ float g_csra[E_];
__device__ float g_scal[N_ * 4];
__device__ float g_dval[N_];
__device__ float g_u[512];
__device__ float g_ce[512];
__device__ float g_Wpre[100 * 1000];
__device__ float g_bnS[H_], g_bnQ[H_], g_bnsc[H_], g_bnsh[H_];
__device__ float g_gsum[B_ * H_], g_gcnt[B_];

__global__ void k_zero() {
    int tot = N_ + N_ + B_ * H_ + B_;
    for (int idx = blockIdx.x * blockDim.x + threadIdx.x; idx < tot; idx += gridDim.x * blockDim.x) {
        if (idx < N_)                      g_cnt[idx] = 0;
        else if (idx < 2 * N_)             g_wp[idx - N_] = 0;
        else if (idx < 2 * N_ + B_ * H_)   g_gsum[idx - 2 * N_] = 0.f;
        else                               g_gcnt[idx - 2 * N_ - B_ * H_] = 0.f;
    }
}

__global__ void k_count(const int* __restrict__ ei) {
    const int* dst = ei + E_;
    for (int e = blockIdx.x * blockDim.x + threadIdx.x; e < E_; e += gridDim.x * blockDim.x)
        atomicAdd(&g_cnt[dst[e]], 1);
}

__global__ void k_scan() {
    __shared__ float sred[1024], lred[1024];
    __shared__ int scn[1024];
    __shared__ float s_ag, s_al;
    int tid = threadIdx.x;
    float sc = 0.f, sl = 0.f;
    for (int n = tid; n < N_; n += 1024) { int c = g_cnt[n]; sc += (float)c; sl += logf((float)c + 1.f); }
    sred[tid] = sc; lred[tid] = sl;
    __syncthreads();
    for (int off = 512; off > 0; off >>= 1) {
        if (tid < off) { sred[tid] += sred[tid + off]; lred[tid] += lred[tid + off]; }
        __syncthreads();
    }
    if (tid == 0) { s_al = sred[0] / (float)N_; s_ag = lred[0] / (float)N_; }
    __syncthreads();
    float avlin = s_al, avlog = s_ag;
    const int CH = 20;
    int start = tid * CH, end = min(start + CH, N_);
    int loc = 0;
    for (int n = start; n < end; n++) loc += g_cnt[n];
    scn[tid] = loc;
    __syncthreads();
    for (int off = 1; off < 1024; off <<= 1) {
        int v = (tid >= off) ? scn[tid - off] : 0;
        __syncthreads();
        scn[tid] += v;
        __syncthreads();
    }
    int off0 = scn[tid] - loc;
    for (int n = start; n < end; n++) {
        int c = g_cnt[n];
        g_rowoff[n] = off0; off0 += c;
        float d = (float)max(c, 1);
        float ld = logf(d + 1.f);
        g_dval[n] = d;
        g_scal[n * 4 + 0] = 1.f;
        g_scal[n * 4 + 1] = ld / avlog;
        g_scal[n * 4 + 2] = avlog / ld;
        g_scal[n * 4 + 3] = d / avlin;
    }
    if (tid == 0) g_rowoff[N_] = E_;
}

__global__ void k_scatter(const int* __restrict__ ei, const float* __restrict__ ea) {
    const int* src = ei;
    const int* dst = ei + E_;
    for (int e = blockIdx.x * blockDim.x + threadIdx.x; e < E_; e += gridDim.x * blockDim.x) {
        int d = dst[e];
        int slot = g_rowoff[d] + atomicAdd(&g_wp[d], 1);
        g_csrs[slot] = src[e];
        g_csra[slot] = ea[e];
    }
}

// pack Wpre[k][j]: j<Tg -> w_i[t][k][o], j>=Tg -> w_j ; also zero BN accumulators
__global__ void k_pack(const float* __restrict__ pw, int f) {
    if (blockIdx.x == 0 && threadIdx.x < H_) { g_bnS[threadIdx.x] = 0.f; g_bnQ[threadIdx.x] = 0.f; }
    int Tg = T_ * f, J = 2 * Tg, tot = f * J;
    for (int idx = blockIdx.x * blockDim.x + threadIdx.x; idx < tot; idx += gridDim.x * blockDim.x) {
        int k = idx / J, j = idx % J;
        float w;
        if (j < Tg) { int t = j / f, o = j % f; w = pw[(size_t)(t * 3 * f + k) * f + o]; }
        else        { int j2 = j - Tg; int t = j2 / f, o = j2 % f; w = pw[(size_t)(t * 3 * f + f + k) * f + o]; }
        g_Wpre[idx] = w;
    }
}

__global__ void k_uc(const float* __restrict__ pw, const float* __restrict__ ew,
                     const float* __restrict__ eb, const float* __restrict__ pb, int f) {
    int tid = threadIdx.x, Tg = T_ * f;
    if (tid < Tg) {
        int t = tid / f, o = tid % f;
        const float* base = pw + ((size_t)t * 3 * f + 2 * f) * f + o;
        float su = 0.f, sc = 0.f;
        for (int k = 0; k < f; k++) {
            float w = base[(size_t)k * f];
            su = fmaf(ew[k], w, su);
            sc = fmaf(eb[k], w, sc);
        }
        g_u[tid] = su;
        g_ce[tid] = sc + pb[tid];
    }
}

// generic tiled GEMM: C = A(MxK) @ B(KxN) [+ bias]
__global__ void k_gemm(const float* __restrict__ A, const float* __restrict__ Bm,
                       const float* __restrict__ bias, float* __restrict__ C,
                       int M, int K, int Nc) {
    __shared__ float As[16][65];
    __shared__ float Bs[16][64];
    int tid = threadIdx.x, tx = tid % 16, ty = tid / 16;
    int m0 = blockIdx.y * 64, n0 = blockIdx.x * 64;
    float acc[4][4];
#pragma unroll
    for (int i = 0; i < 4; i++)
#pragma unroll
        for (int j = 0; j < 4; j++) acc[i][j] = 0.f;
    for (int k0 = 0; k0 < K; k0 += 16) {
        for (int idx = tid; idx < 1024; idx += 256) {
            int r = idx >> 4, c = idx & 15;
            int mm = m0 + r, kk = k0 + c;
            As[c][r] = (mm < M && kk < K) ? A[(size_t)mm * K + kk] : 0.f;
        }
        for (int idx = tid; idx < 1024; idx += 256) {
            int c = idx >> 6, j = idx & 63;
            int kk = k0 + c, nn = n0 + j;
            Bs[c][j] = (kk < K && nn < Nc) ? Bm[(size_t)kk * Nc + nn] : 0.f;
        }
        __syncthreads();
#pragma unroll
        for (int kk = 0; kk < 16; kk++) {
            float a[4], b[4];
#pragma unroll
            for (int i = 0; i < 4; i++) a[i] = As[kk][ty * 4 + i];
#pragma unroll
            for (int j = 0; j < 4; j++) b[j] = Bs[kk][tx * 4 + j];
#pragma unroll
            for (int i = 0; i < 4; i++)
#pragma unroll
                for (int j = 0; j < 4; j++) acc[i][j] = fmaf(a[i], b[j], acc[i][j]);
        }
        __syncthreads();
    }
    for (int i = 0; i < 4; i++) {
        int mm = m0 + ty * 4 + i;
        if (mm < M)
            for (int j = 0; j < 4; j++) {
                int nn = n0 + tx * 4 + j;
                if (nn < Nc) C[(size_t)mm * Nc + nn] = acc[i][j] + (bias ? bias[nn] : 0.f);
            }
    }
}

// one block per node: message construct + sum/sq/min/max over incoming edges
__global__ void k_agg(int TG, int J, int g) {
    __shared__ int eS[128];
    __shared__ float aS[128];
    int n = blockIdx.x, tid = threadIdx.x;
    float pd = 0.f, uu = 0.f, cc = 0.f;
    if (tid < TG) { pd = g_P[(size_t)n * J + tid]; uu = g_u[tid]; cc = g_ce[tid]; }
    float sum = 0.f, sq = 0.f, mn = INFINITY, mx = -INFINITY;
    int base = g_rowoff[n];
    int deg = g_rowoff[n + 1] - base;
    for (int ch = 0; ch < deg; ch += 128) {
        int m = min(128, deg - ch);
        __syncthreads();
        if (tid < m) { eS[tid] = g_csrs[base + ch + tid]; aS[tid] = g_csra[base + ch + tid]; }
        __syncthreads();
        if (tid < TG) {
            for (int i = 0; i < m; i++) {
                float mv = pd + g_P[(size_t)eS[i] * J + TG + tid] + fmaf(aS[i], uu, cc);
                sum += mv;
                sq = fmaf(mv, mv, sq);
                mn = fminf(mn, mv);
                mx = fmaxf(mx, mv);
            }
        }
    }
    if (tid < TG) {
        float d = g_dval[n];
        float mean = sum / d, ms = sq / d;
        float sd = sqrtf(fmaxf(ms - mean * mean, 0.f) + EPSF);
        if (deg == 0) { mn = 0.f; mx = 0.f; }
        int t = tid / g, c = tid - t * g;
        size_t b = ((size_t)n * T_ + t) * (size_t)(4 * g);
        g_AGG[b + c] = mean;
        g_AGG[b + g + c] = mn;
        g_AGG[b + 2 * g + c] = mx;
        g_AGG[b + 3 * g + c] = sd;
    }
}

// post: h[n,t,o] = sum over 17 K-chunks of f; chunk 0 = x, chunk j = scal_s*agg_part
__global__ void k_post(const float* __restrict__ xin, const float* __restrict__ qw,
                       const float* __restrict__ qb, int f) {
    __shared__ float actS[32][FPAD];
    __shared__ float wT[FO_][FPAD];
    __shared__ float scalS[32][4];
    int tid = threadIdx.x;
    int n0 = blockIdx.x * 32;
    int oh = tid % 10, rg = tid / 10;  // rg 0..15: rows rg*2, rg*2+1; cols oh, oh+10
    if (tid < 128) scalS[tid >> 2][tid & 3] = g_scal[(n0 + (tid >> 2)) * 4 + (tid & 3)];
    for (int t = 0; t < T_; t++) {
        float a00 = 0.f, a01 = 0.f, a10 = 0.f, a11 = 0.f;
        const float* qwt = qw + (size_t)t * 17 * f * FO_;
        for (int j = 0; j < 17; j++) {
            __syncthreads();
            if (j == 0) {
                for (int idx = tid; idx < 32 * f; idx += 160) {
                    int r = idx / f, k = idx - r * f;
                    actS[r][k] = xin[(size_t)(n0 + r) * f + k];
                }
            } else {
                int s = (j - 1) >> 2, p = (j - 1) & 3;
                for (int idx = tid; idx < 32 * f; idx += 160) {
                    int r = idx / f, k = idx - r * f;
                    actS[r][k] = scalS[r][s] * g_AGG[((size_t)(n0 + r) * T_ + t) * (4 * f) + p * f + k];
                }
            }
            for (int idx = tid; idx < f * FO_; idx += 160) {
                int k = idx / FO_, o = idx - k * FO_;
                wT[o][k] = qwt[(size_t)(j * f + k) * FO_ + o];
            }
            __syncthreads();
            const float* A0 = actS[rg * 2];
            const float* A1 = actS[rg * 2 + 1];
            const float* Wa = wT[oh];
            const float* Wb = wT[oh + 10];
            for (int k = 0; k < f; k += 2) {
                float2 a0 = *(const float2*)(A0 + k), a1 = *(const float2*)(A1 + k);
                float2 wa = *(const float2*)(Wa + k), wb = *(const float2*)(Wb + k);
                a00 = fmaf(a0.x, wa.x, fmaf(a0.y, wa.y, a00));
                a01 = fmaf(a0.x, wb.x, fmaf(a0.y, wb.y, a01));
                a10 = fmaf(a1.x, wa.x, fmaf(a1.y, wa.y, a10));
                a11 = fmaf(a1.x, wb.x, fmaf(a1.y, wb.y, a11));
            }
        }
        float b0 = qb[t * FO_ + oh], b1 = qb[t * FO_ + oh + 10];
        int n = n0 + rg * 2;
        g_XH[(size_t)n * (T_ * FO_) + t * FO_ + oh] = a00 + b0;
        g_XH[(size_t)n * (T_ * FO_) + t * FO_ + oh + 10] = a01 + b1;
        g_XH[(size_t)(n + 1) * (T_ * FO_) + t * FO_ + oh] = a10 + b0;
        g_XH[(size_t)(n + 1) * (T_ * FO_) + t * FO_ + oh + 10] = a11 + b1;
    }
}

__global__ void k_bnstat(const float* __restrict__ X) {
    __shared__ float ss[H_], sq[H_];
    int tid = threadIdx.x;
    if (tid < H_) { ss[tid] = 0.f; sq[tid] = 0.f; }
    __syncthreads();
    for (size_t idx = (size_t)blockIdx.x * blockDim.x + tid; idx < (size_t)N_ * H_;
         idx += (size_t)gridDim.x * blockDim.x) {
        float v = X[idx];
        int c = (int)(idx % H_);
        atomicAdd(&ss[c], v);
        atomicAdd(&sq[c], v * v);
    }
    __syncthreads();
    if (tid < H_) { atomicAdd(&g_bnS[tid], ss[tid]); atomicAdd(&g_bnQ[tid], sq[tid]); }
}

__global__ void k_bnfin(const float* __restrict__ g, const float* __restrict__ b) {
    int tid = threadIdx.x;
    if (tid < H_) {
        float mean = g_bnS[tid] / (float)N_;
        float var = fmaxf(g_bnQ[tid] / (float)N_ - mean * mean, 0.f);
        float sc = g[tid] * rsqrtf(var + EPSF);
        g_bnsc[tid] = sc;
        g_bnsh[tid] = b[tid] - mean * sc;
    }
}

__global__ void k_bnapply() {
    for (int idx = blockIdx.x * blockDim.x + threadIdx.x; idx < N_ * H_; idx += gridDim.x * blockDim.x) {
        int c = idx % H_;
        g_XB[idx] = fmaxf(fmaf(g_XA[idx], g_bnsc[c], g_bnsh[c]), 0.f);
    }
}

__global__ void k_pool(const int* __restrict__ batch) {
    for (int idx = blockIdx.x * blockDim.x + threadIdx.x; idx < N_ * H_; idx += gridDim.x * blockDim.x) {
        int n = idx / H_, h = idx - n * H_;
        int b = batch[n];
        atomicAdd(&g_gsum[b * H_ + h], g_XB[idx]);
        if (h == 0) atomicAdd(&g_gcnt[b], 1.f);
    }
}

__global__ void k_mlp(const float* __restrict__ w1, const float* __restrict__ b1,
                      const float* __restrict__ w2, const float* __restrict__ b2,
                      const float* __restrict__ w3, const float* __restrict__ b3,
                      float* __restrict__ out) {
    __shared__ float gS[B_][H_];
    __shared__ float h1[B_][50];
    __shared__ float h2[B_][25];
    int tid = threadIdx.x;
    for (int idx = tid; idx < B_ * H_; idx += 256) {
        int b = idx / H_;
        gS[b][idx - b * H_] = g_gsum[idx] / fmaxf(g_gcnt[b], 1.f);
    }
    __syncthreads();
    for (int idx = tid; idx < B_ * 50; idx += 256) {
        int b = idx / 50, j = idx - b * 50;
        float s = b1[j];
        for (int k = 0; k < H_; k++) s = fmaf(gS[b][k], w1[k * 50 + j], s);
        h1[b][j] = fmaxf(s, 0.f);
    }
    __syncthreads();
    for (int idx = tid; idx < B_ * 25; idx += 256) {
        int b = idx / 25, j = idx - b * 25;
        float s = b2[j];
        for (int k = 0; k < 50; k++) s = fmaf(h1[b][k], w2[k * 25 + j], s);
        h2[b][j] = fmaxf(s, 0.f);
    }
    __syncthreads();
    if (tid < B_) {
        float s = b3[0];
        for (int k = 0; k < 25; k++) s = fmaf(h2[tid][k], w3[k], s);
        out[tid] = s;
    }
}

extern "C" void kernel_launch(void* const* d_in, const int* in_sizes, int n_in,
                              void* d_out, int out_size) {
    (void)n_in; (void)out_size;
    bool dict = (in_sizes[1] == 2 * E_);
    const float* x = (const float*)d_in[0];
    const int* ei;
    const float* ea;
    const int* batch;
    int wb;
    if (dict) {
        ei = (const int*)d_in[1];
        ea = (const float*)d_in[2];
        batch = (const int*)d_in[3];
        wb = 4;
    } else {
        ea = (const float*)d_in[1];
        ei = (const int*)d_in[28];
        batch = (const int*)d_in[29];
        wb = 2;
    }
    const float* W[26];
    for (int i = 0; i < 26; i++) W[i] = (const float*)d_in[wb + i];
    float* out = (float*)d_out;

    void *pP, *pXH, *pXA, *pXB, *pWpre;
    cudaGetSymbolAddress(&pP, g_P);
    cudaGetSymbolAddress(&pXH, g_XH);
    cudaGetSymbolAddress(&pXA, g_XA);
    cudaGetSymbolAddress(&pXB, g_XB);
    cudaGetSymbolAddress(&pWpre, g_Wpre);

    k_zero<<<120, 256>>>();
    k_count<<<640, 512>>>(ei);
    k_scan<<<1, 1024>>>();
    k_scatter<<<640, 512>>>(ei, ea);

    for (int L = 0; L < 3; L++) {
        int f = L ? H_ : FI_;
        int Tg = T_ * f, J = 2 * Tg;
        const float *ew, *eb, *pw, *pb, *qw, *qb, *lw, *lb, *bng, *bnb;
        if (L == 0) {
            ew = W[0]; eb = W[1]; pw = W[2]; pb = W[3]; qw = W[4]; qb = W[5];
            lw = W[6]; lb = W[7]; bng = W[8]; bnb = W[9];
        } else {
            int i = L - 1;
            ew = W[10] + i * H_;
            eb = W[11] + i * H_;
            pw = W[12] + (size_t)i * T_ * 3 * H_ * H_;
            pb = W[13] + i * T_ * H_;
            qw = W[14] + (size_t)i * T_ * 17 * H_ * FO_;
            qb = W[15] + i * T_ * FO_;
            lw = W[16] + i * H_ * H_;
            lb = W[17] + i * H_;
            bng = W[18] + i * H_;
            bnb = W[19] + i * H_;
        }
        const float* xin = L ? (const float*)pXB : x;
        k_pack<<<128, 256>>>(pw, f);
        k_uc<<<1, 512>>>(pw, ew, eb, pb, f);
        dim3 gp((J + 63) / 64, (N_ + 63) / 64);
        k_gemm<<<gp, 256>>>(xin, (const float*)pWpre, nullptr, (float*)pP, N_, f, J);
        k_agg<<<N_, L ? 512 : 128>>>(Tg, J, f);
        k_post<<<N_ / 32, 160>>>(xin, qw, qb, f);
        dim3 gl((H_ + 63) / 64, (N_ + 63) / 64);
        k_gemm<<<gl, 256>>>((const float*)pXH, lw, lb, (float*)pXA, N_, H_, H_);
        k_bnstat<<<256, 256>>>((const float*)pXA);
        k_bnfin<<<1, 128>>>(bng, bnb);
        k_bnapply<<<1024, 256>>>();
    }
    k_pool<<<1024, 256>>>(batch);
    k_mlp<<<1, 256>>>(W[20], W[21], W[22], W[23], W[24], W[25], out);
}

// round 3
// speedup vs baseline: 1.0896x; 1.0896x over previous
#include <cuda_runtime.h>
#include <math.h>

#define N_ 20000
#define E_ 320000
#define T_ 5
#define FO_ 20
#define B_ 50
#define H_ 100
#define FI_ 16
#define EPSF 1e-5f

typedef unsigned long long ull;

__device__ float g_P[(size_t)N_ * 1000];     // [n][0..Tg)=P_i, [Tg..2Tg)=P_j
__device__ float g_AGG[(size_t)N_ * 2000];   // [n][t][mean|min|max|std] (4f per tower)
__device__ float g_XH[N_ * H_];
__device__ float g_XA[N_ * H_];
__device__ float g_XB[N_ * H_];
__device__ int   g_cnt[N_];
__device__ int   g_rowoff[N_ + 1];
__device__ int   g_wp[N_];
__device__ int   g_csrs[E_];
__device__ float g_csra[E_];
__device__ float g_scal[N_ * 4];
__device__ float g_dval[N_];
__device__ float g_u[512];
__device__ float g_ce[512];
__device__ float g_Wpre[100 * 1000];
__device__ float g_bnS[H_], g_bnQ[H_], g_bnsc[H_], g_bnsh[H_];
__device__ float g_gsum[B_ * H_], g_gcnt[B_];

__device__ __forceinline__ ull fma2(ull a, ull b, ull c) {
    ull d;
    asm("fma.rn.f32x2 %0, %1, %2, %3;" : "=l"(d) : "l"(a), "l"(b), "l"(c));
    return d;
}
__device__ __forceinline__ ull mul2(ull a, ull b) {
    ull d;
    asm("mul.rn.f32x2 %0, %1, %2;" : "=l"(d) : "l"(a), "l"(b));
    return d;
}
__device__ __forceinline__ ull pack2(float x) {
    ull d;
    asm("mov.b64 %0, {%1, %1};" : "=l"(d) : "f"(x));
    return d;
}
__device__ __forceinline__ float red2(ull v) {
    float lo = __uint_as_float((unsigned)(v & 0xffffffffull));
    float hi = __uint_as_float((unsigned)(v >> 32));
    return lo + hi;
}
__device__ __forceinline__ ull ld2(const float* p) {
    return *reinterpret_cast<const ull*>(p);
}

__global__ void k_zero() {
    int tot = N_ + N_ + B_ * H_ + B_;
    for (int idx = blockIdx.x * blockDim.x + threadIdx.x; idx < tot; idx += gridDim.x * blockDim.x) {
        if (idx < N_)                      g_cnt[idx] = 0;
        else if (idx < 2 * N_)             g_wp[idx - N_] = 0;
        else if (idx < 2 * N_ + B_ * H_)   g_gsum[idx - 2 * N_] = 0.f;
        else                               g_gcnt[idx - 2 * N_ - B_ * H_] = 0.f;
    }
}

__global__ void k_count(const int* __restrict__ ei) {
    const int* dst = ei + E_;
    for (int e = blockIdx.x * blockDim.x + threadIdx.x; e < E_; e += gridDim.x * blockDim.x)
        atomicAdd(&g_cnt[dst[e]], 1);
}

__global__ void k_scan() {
    __shared__ float sred[1024], lred[1024];
    __shared__ int scn[1024];
    __shared__ float s_ag, s_al;
    int tid = threadIdx.x;
    float sc = 0.f, sl = 0.f;
    for (int n = tid; n < N_; n += 1024) { int c = g_cnt[n]; sc += (float)c; sl += logf((float)c + 1.f); }
    sred[tid] = sc; lred[tid] = sl;
    __syncthreads();
    for (int off = 512; off > 0; off >>= 1) {
        if (tid < off) { sred[tid] += sred[tid + off]; lred[tid] += lred[tid + off]; }
        __syncthreads();
    }
    if (tid == 0) { s_al = sred[0] / (float)N_; s_ag = lred[0] / (float)N_; }
    __syncthreads();
    float avlin = s_al, avlog = s_ag;
    const int CH = 20;
    int start = tid * CH, end = min(start + CH, N_);
    int loc = 0;
    for (int n = start; n < end; n++) loc += g_cnt[n];
    scn[tid] = loc;
    __syncthreads();
    for (int off = 1; off < 1024; off <<= 1) {
        int v = (tid >= off) ? scn[tid - off] : 0;
        __syncthreads();
        scn[tid] += v;
        __syncthreads();
    }
    int off0 = scn[tid] - loc;
    for (int n = start; n < end; n++) {
        int c = g_cnt[n];
        g_rowoff[n] = off0; off0 += c;
        float d = (float)max(c, 1);
        float ld = logf(d + 1.f);
        g_dval[n] = d;
        g_scal[n * 4 + 0] = 1.f;
        g_scal[n * 4 + 1] = ld / avlog;
        g_scal[n * 4 + 2] = avlog / ld;
        g_scal[n * 4 + 3] = d / avlin;
    }
    if (tid == 0) g_rowoff[N_] = E_;
}

__global__ void k_scatter(const int* __restrict__ ei, const float* __restrict__ ea) {
    const int* src = ei;
    const int* dst = ei + E_;
    for (int e = blockIdx.x * blockDim.x + threadIdx.x; e < E_; e += gridDim.x * blockDim.x) {
        int d = dst[e];
        int slot = g_rowoff[d] + atomicAdd(&g_wp[d], 1);
        g_csrs[slot] = src[e];
        g_csra[slot] = ea[e];
    }
}

__global__ void k_pack(const float* __restrict__ pw, int f) {
    if (blockIdx.x == 0 && threadIdx.x < H_) { g_bnS[threadIdx.x] = 0.f; g_bnQ[threadIdx.x] = 0.f; }
    int Tg = T_ * f, J = 2 * Tg, tot = f * J;
    for (int idx = blockIdx.x * blockDim.x + threadIdx.x; idx < tot; idx += gridDim.x * blockDim.x) {
        int k = idx / J, j = idx % J;
        float w;
        if (j < Tg) { int t = j / f, o = j % f; w = pw[(size_t)(t * 3 * f + k) * f + o]; }
        else        { int j2 = j - Tg; int t = j2 / f, o = j2 % f; w = pw[(size_t)(t * 3 * f + f + k) * f + o]; }
        g_Wpre[idx] = w;
    }
}

__global__ void k_uc(const float* __restrict__ pw, const float* __restrict__ ew,
                     const float* __restrict__ eb, const float* __restrict__ pb, int f) {
    int tid = threadIdx.x, Tg = T_ * f;
    if (tid < Tg) {
        int t = tid / f, o = tid % f;
        const float* base = pw + ((size_t)t * 3 * f + 2 * f) * f + o;
        float su = 0.f, sc = 0.f;
        for (int k = 0; k < f; k++) {
            float w = base[(size_t)k * f];
            su = fmaf(ew[k], w, su);
            sc = fmaf(eb[k], w, sc);
        }
        g_u[tid] = su;
        g_ce[tid] = sc + pb[tid];
    }
}

// tiled GEMM with interleaved row/col ownership + f32x2: C = A(MxK)@B(KxN) [+bias]
__global__ void __launch_bounds__(256) k_gemm2(const float* __restrict__ A, const float* __restrict__ Bm,
                        const float* __restrict__ bias, float* __restrict__ C,
                        int M, int K, int Nc) {
    __shared__ float As[64 * 18];
    __shared__ float Bs[64 * 18];
    int tid = threadIdx.x;
    int ty = tid & 15, tx = tid >> 4;
    int m0 = blockIdx.y * 64, n0 = blockIdx.x * 64;
    ull acc[4][4];
#pragma unroll
    for (int i = 0; i < 4; i++)
#pragma unroll
        for (int j = 0; j < 4; j++) acc[i][j] = 0ull;
    for (int k0 = 0; k0 < K; k0 += 16) {
        __syncthreads();
        for (int it = 0; it < 4; it++) {
            int idx = tid + it * 256;
            int r = idx >> 4, k = idx & 15;
            int mm = m0 + r, kk = k0 + k;
            As[r * 18 + k] = (mm < M && kk < K) ? A[(size_t)mm * K + kk] : 0.f;
        }
        for (int it = 0; it < 4; it++) {
            int idx = tid + it * 256;
            int k = idx >> 6, c = idx & 63;
            int kk = k0 + k, nn = n0 + c;
            Bs[c * 18 + k] = (kk < K && nn < Nc) ? Bm[(size_t)kk * Nc + nn] : 0.f;
        }
        __syncthreads();
#pragma unroll
        for (int kp = 0; kp < 8; kp++) {
            ull a[4], b[4];
#pragma unroll
            for (int i = 0; i < 4; i++) a[i] = ld2(As + (ty + 16 * i) * 18 + kp * 2);
#pragma unroll
            for (int j = 0; j < 4; j++) b[j] = ld2(Bs + (tx + 16 * j) * 18 + kp * 2);
#pragma unroll
            for (int i = 0; i < 4; i++)
#pragma unroll
                for (int j = 0; j < 4; j++) acc[i][j] = fma2(a[i], b[j], acc[i][j]);
        }
    }
#pragma unroll
    for (int i = 0; i < 4; i++) {
        int mm = m0 + ty + 16 * i;
        if (mm < M) {
#pragma unroll
            for (int j = 0; j < 4; j++) {
                int nn = n0 + tx + 16 * j;
                if (nn < Nc) C[(size_t)mm * Nc + nn] = red2(acc[i][j]) + (bias ? bias[nn] : 0.f);
            }
        }
    }
}

// one block per node: message construct + sum/sq/min/max over incoming edges
__global__ void k_agg(int TG, int J, int g) {
    __shared__ int eS[128];
    __shared__ float aS[128];
    int n = blockIdx.x, tid = threadIdx.x;
    float pd = 0.f, uu = 0.f, cc = 0.f;
    if (tid < TG) { pd = g_P[(size_t)n * J + tid]; uu = g_u[tid]; cc = g_ce[tid]; }
    float sum = 0.f, sq = 0.f, mn = INFINITY, mx = -INFINITY;
    int base = g_rowoff[n];
    int deg = g_rowoff[n + 1] - base;
    for (int ch = 0; ch < deg; ch += 128) {
        int m = min(128, deg - ch);
        __syncthreads();
        if (tid < m) { eS[tid] = g_csrs[base + ch + tid]; aS[tid] = g_csra[base + ch + tid]; }
        __syncthreads();
        if (tid < TG) {
            for (int i = 0; i < m; i++) {
                float mv = pd + g_P[(size_t)eS[i] * J + TG + tid] + fmaf(aS[i], uu, cc);
                sum += mv;
                sq = fmaf(mv, mv, sq);
                mn = fminf(mn, mv);
                mx = fmaxf(mx, mv);
            }
        }
    }
    if (tid < TG) {
        float d = g_dval[n];
        float mean = sum / d, ms = sq / d;
        float sd = sqrtf(fmaxf(ms - mean * mean, 0.f) + EPSF);
        if (deg == 0) { mn = 0.f; mx = 0.f; }
        int t = tid / g, c = tid - t * g;
        size_t b = ((size_t)n * T_ + t) * (size_t)(4 * g);
        g_AGG[b + c] = mean;
        g_AGG[b + g + c] = mn;
        g_AGG[b + 2 * g + c] = mx;
        g_AGG[b + 3 * g + c] = sd;
    }
}

// post v2: 64 nodes x 1 tower per block, 128 threads = 16 rowgrp x 2 colgrp x 4 kslices.
// Thread: 4 interleaved rows x 10 cols, f32x2 accumulators. agg staged once (scal folded
// at read). 17 K-chunks: rounds 0-3 = chunk-per-slice, round 4 = chunk 16 split by k.
__global__ void __launch_bounds__(128) k_post2(const float* __restrict__ xin, const float* __restrict__ qw,
                        const float* __restrict__ qb, int f) {
    extern __shared__ float sm[];
    int XSP = f + 2, ASP = 4 * f + 2, WKP = f + 2;
    float* xS = sm;
    float* aggS = sm + 64 * XSP;
    float* wS = aggS + 64 * ASP;
    int t = blockIdx.y;
    int n0 = blockIdx.x * 64;
    int tid = threadIdx.x;
    int rg = tid & 15, c2 = (tid >> 4) & 1, ks = tid >> 5;
    int f4 = 4 * f;

    for (int idx = tid; idx < 64 * f; idx += 128) {
        int r = idx / f, k = idx - r * f;
        int n = n0 + r; if (n >= N_) n = N_ - 1;
        xS[r * XSP + k] = xin[(size_t)n * f + k];
    }
    for (int idx = tid; idx < 64 * f4; idx += 128) {
        int r = idx / f4, c = idx - r * f4;
        int n = n0 + r; if (n >= N_) n = N_ - 1;
        aggS[r * ASP + c] = g_AGG[((size_t)n * T_ + t) * f4 + c];
    }
    float scv[4][4];
#pragma unroll
    for (int i = 0; i < 4; i++) {
        int n = n0 + rg + 16 * i; if (n >= N_) n = N_ - 1;
#pragma unroll
        for (int s = 0; s < 4; s++) scv[i][s] = g_scal[n * 4 + s];
    }
    const float* qwt = qw + (size_t)t * 17 * f * FO_;
    ull acc[4][10];
#pragma unroll
    for (int i = 0; i < 4; i++)
#pragma unroll
        for (int j = 0; j < 10; j++) acc[i][j] = 0ull;
    int P = f >> 1;

    for (int round = 0; round < 5; round++) {
        __syncthreads();
        int nch = (round < 4) ? 4 : 1;
        for (int b = 0; b < nch; b++) {
            int j = round * 4 + b;
            const float* wsrc = qwt + (size_t)j * f * FO_;
            float* wdst = wS + b * FO_ * WKP;
            for (int idx = tid; idx < f * FO_; idx += 128) {
                int k = idx / FO_, o = idx - k * FO_;
                wdst[o * WKP + k] = wsrc[(size_t)k * FO_ + o];
            }
        }
        __syncthreads();
        int j, wbuf, kp0, kp1;
        if (round < 4) { j = round * 4 + ks; wbuf = ks; kp0 = 0; kp1 = P; }
        else {
            j = 16; wbuf = 0;
            int per = (P + 3) >> 2;
            kp0 = ks * per; kp1 = min(kp0 + per, P);
        }
        const float* act;
        int stride;
        ull rs[4];
        if (j == 0) {
            act = xS; stride = XSP;
#pragma unroll
            for (int i = 0; i < 4; i++) rs[i] = pack2(1.0f);
        } else {
            int s = (j - 1) >> 2, p = (j - 1) & 3;
            act = aggS + p * f; stride = ASP;
#pragma unroll
            for (int i = 0; i < 4; i++) rs[i] = pack2(scv[i][s]);
        }
        const float* wb = wS + wbuf * FO_ * WKP + (c2 * 10) * WKP;
        for (int kp = kp0; kp < kp1; kp++) {
            int k = kp * 2;
            ull a[4];
#pragma unroll
            for (int i = 0; i < 4; i++)
                a[i] = mul2(ld2(act + (rg + 16 * i) * stride + k), rs[i]);
#pragma unroll
            for (int jj = 0; jj < 10; jj++) {
                ull w = ld2(wb + jj * WKP + k);
#pragma unroll
                for (int i = 0; i < 4; i++) acc[i][jj] = fma2(a[i], w, acc[i][jj]);
            }
        }
    }

    __syncthreads();
    ull* red = (ull*)sm;
    if (ks > 0) {
        ull* dst = red + (size_t)((ks - 1) * 32 + (tid & 31)) * 40;
#pragma unroll
        for (int i = 0; i < 4; i++)
#pragma unroll
            for (int jj = 0; jj < 10; jj++) dst[i * 10 + jj] = acc[i][jj];
    }
    __syncthreads();
    if (ks == 0) {
        int lane = tid & 31;
#pragma unroll
        for (int i = 0; i < 4; i++) {
            int n = n0 + rg + 16 * i;
            if (n < N_) {
#pragma unroll
                for (int jj = 0; jj < 10; jj++) {
                    float s = red2(acc[i][jj]);
                    for (int sl = 0; sl < 3; sl++)
                        s += red2(red[(size_t)(sl * 32 + lane) * 40 + i * 10 + jj]);
                    int col = c2 * 10 + jj;
                    g_XH[(size_t)n * (T_ * FO_) + t * FO_ + col] = s + qb[t * FO_ + col];
                }
            }
        }
    }
}

__global__ void k_bnstat(const float* __restrict__ X) {
    __shared__ float ss[H_], sq[H_];
    int tid = threadIdx.x;
    if (tid < H_) { ss[tid] = 0.f; sq[tid] = 0.f; }
    __syncthreads();
    for (size_t idx = (size_t)blockIdx.x * blockDim.x + tid; idx < (size_t)N_ * H_;
         idx += (size_t)gridDim.x * blockDim.x) {
        float v = X[idx];
        int c = (int)(idx % H_);
        atomicAdd(&ss[c], v);
        atomicAdd(&sq[c], v * v);
    }
    __syncthreads();
    if (tid < H_) { atomicAdd(&g_bnS[tid], ss[tid]); atomicAdd(&g_bnQ[tid], sq[tid]); }
}

__global__ void k_bnfin(const float* __restrict__ g, const float* __restrict__ b) {
    int tid = threadIdx.x;
    if (tid < H_) {
        float mean = g_bnS[tid] / (float)N_;
        float var = fmaxf(g_bnQ[tid] / (float)N_ - mean * mean, 0.f);
        float sc = g[tid] * rsqrtf(var + EPSF);
        g_bnsc[tid] = sc;
        g_bnsh[tid] = b[tid] - mean * sc;
    }
}

__global__ void k_bnapply() {
    for (int idx = blockIdx.x * blockDim.x + threadIdx.x; idx < N_ * H_; idx += gridDim.x * blockDim.x) {
        int c = idx % H_;
        g_XB[idx] = fmaxf(fmaf(g_XA[idx], g_bnsc[c], g_bnsh[c]), 0.f);
    }
}

__global__ void k_pool(const int* __restrict__ batch) {
    for (int idx = blockIdx.x * blockDim.x + threadIdx.x; idx < N_ * H_; idx += gridDim.x * blockDim.x) {
        int n = idx / H_, h = idx - n * H_;
        int b = batch[n];
        atomicAdd(&g_gsum[b * H_ + h], g_XB[idx]);
        if (h == 0) atomicAdd(&g_gcnt[b], 1.f);
    }
}

__global__ void k_mlp(const float* __restrict__ w1, const float* __restrict__ b1,
                      const float* __restrict__ w2, const float* __restrict__ b2,
                      const float* __restrict__ w3, const float* __restrict__ b3,
                      float* __restrict__ out) {
    __shared__ float gS[B_][H_];
    __shared__ float h1[B_][50];
    __shared__ float h2[B_][25];
    int tid = threadIdx.x;
    for (int idx = tid; idx < B_ * H_; idx += 256) {
        int b = idx / H_;
        gS[b][idx - b * H_] = g_gsum[idx] / fmaxf(g_gcnt[b], 1.f);
    }
    __syncthreads();
    for (int idx = tid; idx < B_ * 50; idx += 256) {
        int b = idx / 50, j = idx - b * 50;
        float s = b1[j];
        for (int k = 0; k < H_; k++) s = fmaf(gS[b][k], w1[k * 50 + j], s);
        h1[b][j] = fmaxf(s, 0.f);
    }
    __syncthreads();
    for (int idx = tid; idx < B_ * 25; idx += 256) {
        int b = idx / 25, j = idx - b * 25;
        float s = b2[j];
        for (int k = 0; k < 50; k++) s = fmaf(h1[b][k], w2[k * 25 + j], s);
        h2[b][j] = fmaxf(s, 0.f);
    }
    __syncthreads();
    if (tid < B_) {
        float s = b3[0];
        for (int k = 0; k < 25; k++) s = fmaf(h2[tid][k], w3[k], s);
        out[tid] = s;
    }
}

extern "C" void kernel_launch(void* const* d_in, const int* in_sizes, int n_in,
                              void* d_out, int out_size) {
    (void)n_in; (void)out_size;
    bool dict = (in_sizes[1] == 2 * E_);
    const float* x = (const float*)d_in[0];
    const int* ei;
    const float* ea;
    const int* batch;
    int wb;
    if (dict) {
        ei = (const int*)d_in[1];
        ea = (const float*)d_in[2];
        batch = (const int*)d_in[3];
        wb = 4;
    } else {
        ea = (const float*)d_in[1];
        ei = (const int*)d_in[28];
        batch = (const int*)d_in[29];
        wb = 2;
    }
    const float* W[26];
    for (int i = 0; i < 26; i++) W[i] = (const float*)d_in[wb + i];
    float* out = (float*)d_out;

    void *pP, *pXH, *pXA, *pXB, *pWpre;
    cudaGetSymbolAddress(&pP, g_P);
    cudaGetSymbolAddress(&pXH, g_XH);
    cudaGetSymbolAddress(&pXA, g_XA);
    cudaGetSymbolAddress(&pXB, g_XB);
    cudaGetSymbolAddress(&pWpre, g_Wpre);

    // max dynamic smem for k_post2 (f=100 layout)
    int smemMax = (64 * 102 + 64 * 402 + 4 * FO_ * 102) * 4;
    cudaFuncSetAttribute(k_post2, cudaFuncAttributeMaxDynamicSharedMemorySize, smemMax);

    k_zero<<<120, 256>>>();
    k_count<<<640, 512>>>(ei);
    k_scan<<<1, 1024>>>();
    k_scatter<<<640, 512>>>(ei, ea);

    for (int L = 0; L < 3; L++) {
        int f = L ? H_ : FI_;
        int Tg = T_ * f, J = 2 * Tg;
        const float *ew, *eb, *pw, *pb, *qw, *qb, *lw, *lb, *bng, *bnb;
        if (L == 0) {
            ew = W[0]; eb = W[1]; pw = W[2]; pb = W[3]; qw = W[4]; qb = W[5];
            lw = W[6]; lb = W[7]; bng = W[8]; bnb = W[9];
        } else {
            int i = L - 1;
            ew = W[10] + i * H_;
            eb = W[11] + i * H_;
            pw = W[12] + (size_t)i * T_ * 3 * H_ * H_;
            pb = W[13] + i * T_ * H_;
            qw = W[14] + (size_t)i * T_ * 17 * H_ * FO_;
            qb = W[15] + i * T_ * FO_;
            lw = W[16] + i * H_ * H_;
            lb = W[17] + i * H_;
            bng = W[18] + i * H_;
            bnb = W[19] + i * H_;
        }
        const float* xin = L ? (const float*)pXB : x;
        k_pack<<<128, 256>>>(pw, f);
        k_uc<<<1, 512>>>(pw, ew, eb, pb, f);
        dim3 gp((J + 63) / 64, (N_ + 63) / 64);
        k_gemm2<<<gp, 256>>>(xin, (const float*)pWpre, nullptr, (float*)pP, N_, f, J);
        k_agg<<<N_, L ? 512 : 128>>>(Tg, J, f);
        int layoutFloats = 64 * (f + 2) + 64 * (4 * f + 2) + 4 * FO_ * (f + 2);
        int redFloats = 96 * 40 * 2;
        int smemB = (layoutFloats > redFloats ? layoutFloats : redFloats) * 4;
        dim3 gq((N_ + 63) / 64, T_);
        k_post2<<<gq, 128, smemB>>>(xin, qw, qb, f);
        dim3 gl((H_ + 63) / 64, (N_ + 63) / 64);
        k_gemm2<<<gl, 256>>>((const float*)pXH, lw, lb, (float*)pXA, N_, H_, H_);
        k_bnstat<<<256, 256>>>((const float*)pXA);
        k_bnfin<<<1, 128>>>(bng, bnb);
        k_bnapply<<<1024, 256>>>();
    }
    k_pool<<<1024, 256>>>(batch);
    k_mlp<<<1, 256>>>(W[20], W[21], W[22], W[23], W[24], W[25], out);
}